// round 1
// baseline (speedup 1.0000x reference)
#include <cuda_runtime.h>
#include <cstring>
#include <math.h>

// Problem constants (match reference)
#define DIMS 20
#define MULT 8
#define KCOMP 168            // (DIMS+1)*MULT
#define NPAIR (DIMS/2)       // 10 f32x2 pairs per sample
#define ROWF 48              // floats per component row in B (20 a + 20 b + c + pad)
#define ROWV 12              // float4 per row
#define LOG_NORM (-18.378770664093453)   // -DIMS/2 * log(2*pi)
#define EPS_VAR 1.0          // EPS^2 with EPS = 1.0
#define BASE_COV 0.1

// Precomputed per-component matrix: for each k,
//   floats [0..19]  : a[d] = -0.5*log2(e) * inv[k][d]          (multiplies x^2)
//   floats [20..39] : b[d] =      log2(e) * inv[k][d]*mu[k][d] (multiplies x)
//   float  [40]     : c    = log2(w_k * sig_k) - 0.5*log2(e)*sum_d mu^2*inv
__device__ float g_B[KCOMP * ROWF];

typedef unsigned long long u64;

__device__ __forceinline__ u64 pack2f(float lo, float hi) {
    u64 r;
    asm("mov.b64 %0, {%1, %2};" : "=l"(r) : "f"(lo), "f"(hi));
    return r;
}
__device__ __forceinline__ void unpack2f(u64 v, float& lo, float& hi) {
    asm("mov.b64 {%0, %1}, %2;" : "=f"(lo), "=f"(hi) : "l"(v));
}
__device__ __forceinline__ u64 ffma2(u64 a, u64 b, u64 c) {
    u64 d;
    asm("fma.rn.f32x2 %0, %1, %2, %3;" : "=l"(d) : "l"(a), "l"(b), "l"(c));
    return d;
}
__device__ __forceinline__ u64 fmul2(u64 a, u64 b) {
    u64 d;
    asm("mul.rn.f32x2 %0, %1, %2;" : "=l"(d) : "l"(a), "l"(b));
    return d;
}
__device__ __forceinline__ u64 fadd2(u64 a, u64 b) {
    u64 d;
    asm("add.rn.f32x2 %0, %1, %2;" : "=l"(d) : "l"(a), "l"(b));
    return d;
}
__device__ __forceinline__ float ex2f(float x) {
    float r;
    asm("ex2.approx.ftz.f32 %0, %1;" : "=f"(r) : "f"(x));
    return r;
}

// ---------------------------------------------------------------------------
// Kernel 1: tiny precompute (softmax over alpha + fold all constants into B).
// Done in double where it matters; cost is negligible (single block).
// ---------------------------------------------------------------------------
__global__ void gm_prep_kernel(const float* __restrict__ alpha,
                               const float* __restrict__ mu,
                               const float* __restrict__ cov) {
    __shared__ float sw[KCOMP];
    int t = threadIdx.x;
    if (t < KCOMP) sw[t] = alpha[t];
    __syncthreads();
    if (t == 0) {
        float m = sw[0];
        for (int k = 1; k < KCOMP; k++) m = fmaxf(m, sw[k]);
        float s = 0.f;
        for (int k = 0; k < KCOMP; k++) { sw[k] = expf(sw[k] - m); s += sw[k]; }
        float invs = 1.f / s;
        for (int k = 0; k < KCOMP; k++) sw[k] *= invs;
    }
    __syncthreads();

    if (t < KCOMP) {
        const int i = t / MULT;               // component group index 0..DIMS
        const double LOG2E = 1.4426950408889634;
        double sum_mu2inv = 0.0;
        for (int d = 0; d < DIMS; d++) {
            float sc = (d < i) ? (float)EPS_VAR : 1.0f;
            double inv = 1.0 / ((double)cov[t * DIMS + d] * (double)sc);
            double m = (double)mu[t * DIMS + d];
            g_B[t * ROWF + d]        = (float)(-0.5 * LOG2E * inv);
            g_B[t * ROWF + DIMS + d] = (float)(LOG2E * inv * m);
            sum_mu2inv += m * m * inv;
        }
        // det_cov = var^i * BASE_COV^(DIMS - i)  (exactly as in the reference)
        double log2det = (double)i * log2((double)EPS_VAR)
                       + (double)(DIMS - i) * log2((double)BASE_COV);
        double c = log2((double)sw[t]) - 0.5 * log2det - 0.5 * LOG2E * sum_mu2inv;
        g_B[t * ROWF + 2 * DIMS] = (float)c;
        // zero the padding so stray reads are harmless
        for (int d = 2 * DIMS + 1; d < ROWF; d++) g_B[t * ROWF + d] = 0.f;
    }
}

// ---------------------------------------------------------------------------
// Kernel 2: main evaluation. One thread = one sample. Dims are processed as
// f32x2 pairs (FFMA2): B pairs come straight out of shared via LDS.128,
// x / x^2 pairs live packed in registers — no repacking in the hot loop.
// ---------------------------------------------------------------------------
__global__ void __launch_bounds__(256)
gm_main_kernel(const float* __restrict__ sample, float* __restrict__ out, int n_total) {
    __shared__ float sB[KCOMP * ROWF];      // 32256 B

    // cooperative copy of the B matrix into shared (float4 granularity)
    {
        const float4* src = (const float4*)g_B;
        float4* dst = (float4*)sB;
        for (int idx = threadIdx.x; idx < KCOMP * ROWV; idx += blockDim.x)
            dst[idx] = src[idx];
    }
    __syncthreads();

    const int n = blockIdx.x * blockDim.x + threadIdx.x;
    if (n >= n_total) return;

    // Load this sample's 20 dims as 10 packed f32x2 pairs; square them once.
    u64 xv[NPAIR];   // (x[2j], x[2j+1])
    u64 xx[NPAIR];   // (x^2)
    {
        const float2* xr = (const float2*)(sample + (size_t)n * DIMS);
        #pragma unroll
        for (int j = 0; j < NPAIR; j++) {
            float2 p = xr[j];
            u64 pp = pack2f(p.x, p.y);
            xv[j] = pp;
            xx[j] = fmul2(pp, pp);
        }
    }

    const float4* rows = (const float4*)sB;
    float density = 0.f;

    #pragma unroll 2
    for (int k = 0; k < KCOMP; k++) {
        const float4* row = rows + k * ROWV;
        u64 acc0, acc1;
        // a-section: multiplies x^2 pairs
        {
            float4 q0 = row[0];
            acc0 = fmul2(xx[0], pack2f(q0.x, q0.y));
            acc1 = fmul2(xx[1], pack2f(q0.z, q0.w));
        }
        #pragma unroll
        for (int j = 1; j < 5; j++) {
            float4 q = row[j];
            acc0 = ffma2(xx[2 * j],     pack2f(q.x, q.y), acc0);
            acc1 = ffma2(xx[2 * j + 1], pack2f(q.z, q.w), acc1);
        }
        // b-section: multiplies x pairs
        #pragma unroll
        for (int j = 0; j < 5; j++) {
            float4 q = row[5 + j];
            acc0 = ffma2(xv[2 * j],     pack2f(q.x, q.y), acc0);
            acc1 = ffma2(xv[2 * j + 1], pack2f(q.z, q.w), acc1);
        }
        u64 acc = fadd2(acc0, acc1);
        float lo, hi;
        unpack2f(acc, lo, hi);
        float c = row[10].x;
        float tkv = c + (lo + hi);
        density += ex2f(tkv);
    }

    out[n] = logf(density) + (float)LOG_NORM;
}

extern "C" void kernel_launch(void* const* d_in, const int* in_sizes, int n_in,
                              void* d_out, int out_size) {
    const float* sample = (const float*)d_in[0];
    const float* alpha  = (const float*)d_in[1];
    const float* mu     = (const float*)d_in[2];
    const float* cov    = (const float*)d_in[3];
    float* out = (float*)d_out;

    const int n_total = in_sizes[0] / DIMS;

    gm_prep_kernel<<<1, 256>>>(alpha, mu, cov);

    const int threads = 256;
    const int blocks = (n_total + threads - 1) / threads;
    gm_main_kernel<<<blocks, threads>>>(sample, out, n_total);
}

// round 2
// speedup vs baseline: 1.2051x; 1.2051x over previous
#include <cuda_runtime.h>
#include <cstring>
#include <math.h>

#define DIMS 20
#define MULT 8
#define KCOMP 168            // (DIMS+1)*MULT
#define NPAIR (DIMS/2)
#define ROWF 48              // 20 a + 20 b + (c,0) + pad
#define ROWV 12
#define LOG_NORM (-18.378770664093453)
#define EPS_VAR 1.0
#define BASE_COV 0.1
#define SPT 4                // samples per thread per iteration

// Per-component precomputed row (ROWF floats):
//   [0..19]  a[d] = -0.5*log2(e)*inv[k][d]        (Horner: multiplies x inner)
//   [20..39] b[d] =      log2(e)*inv[k][d]*mu[k][d]
//   [40]     c    = log2(w_k) - 0.5*log2(det) - 0.5*log2(e)*sum mu^2*inv
//   [41]     0.0  (so (c,0) loads as one float2 -> f32x2 acc init)
__device__ float g_B[KCOMP * ROWF];

typedef unsigned long long u64;

__device__ __forceinline__ u64 pack2f(float lo, float hi) {
    u64 r; asm("mov.b64 %0, {%1, %2};" : "=l"(r) : "f"(lo), "f"(hi)); return r;
}
__device__ __forceinline__ void unpack2f(u64 v, float& lo, float& hi) {
    asm("mov.b64 {%0, %1}, %2;" : "=f"(lo), "=f"(hi) : "l"(v));
}
__device__ __forceinline__ u64 ffma2(u64 a, u64 b, u64 c) {
    u64 d; asm("fma.rn.f32x2 %0, %1, %2, %3;" : "=l"(d) : "l"(a), "l"(b), "l"(c)); return d;
}
__device__ __forceinline__ float ex2f(float x) {
    float r; asm("ex2.approx.ftz.f32 %0, %1;" : "=f"(r) : "f"(x)); return r;
}

// ---------------------------------------------------------------------------
// Prep: parallel softmax + constant folding (single block, 256 threads)
// ---------------------------------------------------------------------------
__global__ void gm_prep_kernel(const float* __restrict__ alpha,
                               const float* __restrict__ mu,
                               const float* __restrict__ cov) {
    __shared__ float red[256];
    const int t = threadIdx.x;

    float a = (t < KCOMP) ? alpha[t] : -1e30f;
    red[t] = a;
    __syncthreads();
    for (int s = 128; s > 0; s >>= 1) {
        if (t < s) red[t] = fmaxf(red[t], red[t + s]);
        __syncthreads();
    }
    const float m = red[0];
    __syncthreads();

    float e = (t < KCOMP) ? expf(a - m) : 0.f;
    red[t] = e;
    __syncthreads();
    for (int s = 128; s > 0; s >>= 1) {
        if (t < s) red[t] += red[t + s];
        __syncthreads();
    }
    const float w = e / red[0];

    if (t < KCOMP) {
        const int i = t / MULT;
        const double LOG2E = 1.4426950408889634;
        double sum_mu2inv = 0.0;
        for (int d = 0; d < DIMS; d++) {
            float sc = (d < i) ? (float)EPS_VAR : 1.0f;
            double inv = 1.0 / ((double)cov[t * DIMS + d] * (double)sc);
            double mm = (double)mu[t * DIMS + d];
            g_B[t * ROWF + d]        = (float)(-0.5 * LOG2E * inv);
            g_B[t * ROWF + DIMS + d] = (float)(LOG2E * inv * mm);
            sum_mu2inv += mm * mm * inv;
        }
        double log2det = (double)i * log2((double)EPS_VAR)
                       + (double)(DIMS - i) * log2((double)BASE_COV);
        double c = log2((double)w) - 0.5 * log2det - 0.5 * LOG2E * sum_mu2inv;
        g_B[t * ROWF + 2 * DIMS] = (float)c;
        for (int d = 2 * DIMS + 1; d < ROWF; d++) g_B[t * ROWF + d] = 0.f;
    }
}

// ---------------------------------------------------------------------------
// Main: persistent grid, 4 samples/thread, Horner f32x2 inner loop.
// Per k per sample: acc = c; for each pair: t = fma2(x, A, B); acc = fma2(x, t, acc)
// ---------------------------------------------------------------------------
__global__ void __launch_bounds__(256, 2)
gm_main_kernel(const float* __restrict__ sample, float* __restrict__ out, int n_total) {
    __shared__ float sB[KCOMP * ROWF];      // 32256 B
    {
        const float4* src = (const float4*)g_B;
        float4* dst = (float4*)sB;
        for (int idx = threadIdx.x; idx < KCOMP * ROWV; idx += blockDim.x)
            dst[idx] = src[idx];
    }
    __syncthreads();

    const int TT = gridDim.x * blockDim.x;
    const int gtid = blockIdx.x * blockDim.x + threadIdx.x;

    for (int base = gtid; base < n_total; base += SPT * TT) {
        int nn[SPT];
        bool valid[SPT];
        #pragma unroll
        for (int s = 0; s < SPT; s++) {
            nn[s] = base + s * TT;
            valid[s] = (nn[s] < n_total);
        }

        // Load x for all samples as packed f32x2 pairs (invalid -> sample 0, harmless)
        u64 xv[SPT][NPAIR];
        #pragma unroll
        for (int s = 0; s < SPT; s++) {
            const size_t idx = valid[s] ? (size_t)nn[s] : 0;
            const float2* xr = (const float2*)(sample + idx * DIMS);
            #pragma unroll
            for (int j = 0; j < NPAIR; j++) {
                float2 p = xr[j];
                xv[s][j] = pack2f(p.x, p.y);
            }
        }

        float dens[SPT];
        #pragma unroll
        for (int s = 0; s < SPT; s++) dens[s] = 0.f;

        for (int k = 0; k < KCOMP; k++) {
            const float4* row = (const float4*)(sB + k * ROWF);
            const float2 cc = *(const float2*)(sB + k * ROWF + 2 * DIMS);
            const u64 c2 = pack2f(cc.x, cc.y);          // (c, 0)

            u64 acc[SPT];
            #pragma unroll
            for (int s = 0; s < SPT; s++) acc[s] = c2;

            #pragma unroll
            for (int jj = 0; jj < 5; jj++) {
                const float4 qa = row[jj];       // a-pairs 2jj, 2jj+1
                const float4 qb = row[5 + jj];   // b-pairs 2jj, 2jj+1
                const u64 A0 = pack2f(qa.x, qa.y);
                const u64 A1 = pack2f(qa.z, qa.w);
                const u64 B0 = pack2f(qb.x, qb.y);
                const u64 B1 = pack2f(qb.z, qb.w);
                #pragma unroll
                for (int s = 0; s < SPT; s++) {
                    u64 t;
                    t = ffma2(xv[s][2 * jj], A0, B0);
                    acc[s] = ffma2(xv[s][2 * jj], t, acc[s]);
                    t = ffma2(xv[s][2 * jj + 1], A1, B1);
                    acc[s] = ffma2(xv[s][2 * jj + 1], t, acc[s]);
                }
            }

            #pragma unroll
            for (int s = 0; s < SPT; s++) {
                float lo, hi;
                unpack2f(acc[s], lo, hi);
                dens[s] += ex2f(lo + hi);
            }
        }

        #pragma unroll
        for (int s = 0; s < SPT; s++) {
            if (valid[s]) out[nn[s]] = logf(dens[s]) + (float)LOG_NORM;
        }
    }
}

extern "C" void kernel_launch(void* const* d_in, const int* in_sizes, int n_in,
                              void* d_out, int out_size) {
    const float* sample = (const float*)d_in[0];
    const float* alpha  = (const float*)d_in[1];
    const float* mu     = (const float*)d_in[2];
    const float* cov    = (const float*)d_in[3];
    float* out = (float*)d_out;

    const int n_total = in_sizes[0] / DIMS;

    gm_prep_kernel<<<1, 256>>>(alpha, mu, cov);

    int num_sms = 148;
    cudaDeviceGetAttribute(&num_sms, cudaDevAttrMultiProcessorCount, 0);
    const int blocks = 2 * num_sms;      // 2 resident blocks/SM (launch_bounds)
    gm_main_kernel<<<blocks, 256>>>(sample, out, n_total);
}

// round 4
// speedup vs baseline: 1.9763x; 1.6399x over previous
#include <cuda_runtime.h>
#include <math.h>

#define DIMS 20
#define MULT 8
#define KCOMP 168
#define NPAIR (DIMS/2)
#define ROWF 48              // a[20] | b[20] | c | pad
#define LOG_NORM (-18.378770664093453f)
#define EPS_VAR 1.0f
#define BASE_COV 0.1f
#define LOG2E 1.4426950408889634f
#define SPT 2                // samples per thread per grid-stride chunk

typedef unsigned long long u64;

__device__ __forceinline__ u64 pack2f(float lo, float hi) {
    u64 r; asm("mov.b64 %0, {%1, %2};" : "=l"(r) : "f"(lo), "f"(hi)); return r;
}
__device__ __forceinline__ void unpack2f(u64 v, float& lo, float& hi) {
    asm("mov.b64 {%0, %1}, %2;" : "=f"(lo), "=f"(hi) : "l"(v));
}
__device__ __forceinline__ u64 ffma2(u64 a, u64 b, u64 c) {
    u64 d; asm("fma.rn.f32x2 %0, %1, %2, %3;" : "=l"(d) : "l"(a), "l"(b), "l"(c)); return d;
}
__device__ __forceinline__ u64 fmul2(u64 a, u64 b) {
    u64 d; asm("mul.rn.f32x2 %0, %1, %2;" : "=l"(d) : "l"(a), "l"(b)); return d;
}
__device__ __forceinline__ u64 fadd2(u64 a, u64 b) {
    u64 d; asm("add.rn.f32x2 %0, %1, %2;" : "=l"(d) : "l"(a), "l"(b)); return d;
}
__device__ __forceinline__ float ex2f(float x) {
    float r; asm("ex2.approx.ftz.f32 %0, %1;" : "=f"(r) : "f"(x)); return r;
}

// ---------------------------------------------------------------------------
// Single fused kernel. Stage 1 (per block, redundant, ~2us): softmax + fold
// constants into sB rows + uniformity check. Stage 2: grid-stride main loop.
// Fast path (inv[k][d] identical for all k, true for bench inputs):
//   t[n,k] = A_n + c_k + sum_d g_k[d]*x_d    -> 10 FFMA2 per (n,k)
// General path: full Horner quadratic         -> 20 FFMA2 per (n,k)
// c_k has LOG_NORM*log2e folded in, so out = logf(dens).
// ---------------------------------------------------------------------------
__global__ void __launch_bounds__(256, 2)
gm_fused_kernel(const float* __restrict__ sample,
                const float* __restrict__ alpha,
                const float* __restrict__ mu,
                const float* __restrict__ cov,
                float* __restrict__ out, int n_total) {
    __shared__ float sB[KCOMP * ROWF];      // 32256 B
    __shared__ float red[256];
    __shared__ int sflag;

    const int t = threadIdx.x;
    if (t == 0) sflag = 1;

    // ---- softmax weights over alpha (parallel reduction)
    float av = (t < KCOMP) ? alpha[t] : -1e30f;
    red[t] = av; __syncthreads();
    for (int s = 128; s > 0; s >>= 1) { if (t < s) red[t] = fmaxf(red[t], red[t + s]); __syncthreads(); }
    const float mx = red[0]; __syncthreads();
    float ev = (t < KCOMP) ? expf(av - mx) : 0.f;
    red[t] = ev; __syncthreads();
    for (int s = 128; s > 0; s >>= 1) { if (t < s) red[t] += red[t + s]; __syncthreads(); }
    const float w = ev / red[0];

    // ---- per-component row build + uniformity check
    if (t < KCOMP) {
        const int i = t / MULT;
        float sum_mu2inv = 0.f;
        int ok = 1;
        #pragma unroll
        for (int d = 0; d < DIMS; d++) {
            float sc = (d < i) ? EPS_VAR : 1.0f;
            float inv = 1.0f / (cov[t * DIMS + d] * sc);
            float inv0 = 1.0f / cov[d];                 // k=0 row: i=0, no scaling
            ok &= (inv == inv0);
            float mm = mu[t * DIMS + d];
            sB[t * ROWF + d]        = -0.5f * LOG2E * inv;
            sB[t * ROWF + DIMS + d] =  LOG2E * inv * mm;
            sum_mu2inv += mm * mm * inv;
        }
        float log2det = (float)i * log2f(EPS_VAR) + (float)(DIMS - i) * log2f(BASE_COV);
        sB[t * ROWF + 2 * DIMS] = log2f(w) - 0.5f * log2det
                                - 0.5f * LOG2E * sum_mu2inv
                                + LOG2E * LOG_NORM;     // fold final +LOG_NORM
        #pragma unroll
        for (int f = 2 * DIMS + 1; f < ROWF; f++) sB[t * ROWF + f] = 0.f;
        if (!ok) atomicAnd(&sflag, 0);
    }
    __syncthreads();
    const int uniform = sflag;

    const int TT = gridDim.x * blockDim.x;
    const int gtid = blockIdx.x * blockDim.x + t;

    if (uniform) {
        // ================= FAST PATH =================
        for (int base = gtid; base < n_total; base += SPT * TT) {
            int nn[SPT]; bool valid[SPT];
            u64 xv[SPT][NPAIR];
            u64 AC2[SPT];                 // (A_n, 0)
            float dens[SPT];

            #pragma unroll
            for (int s = 0; s < SPT; s++) {
                nn[s] = base + s * TT;
                valid[s] = (nn[s] < n_total);
                const size_t idx = valid[s] ? (size_t)nn[s] : 0;
                const float2* xr = (const float2*)(sample + idx * DIMS);
                #pragma unroll
                for (int j = 0; j < NPAIR; j++) {
                    float2 p = xr[j];
                    xv[s][j] = pack2f(p.x, p.y);
                }
                // A_n = sum_d a0[d] * x_d^2  (a0 = k=0 a-row; uniform across k)
                u64 acc = fmul2(fmul2(xv[s][0], xv[s][0]),
                                pack2f(sB[0], sB[1]));
                #pragma unroll
                for (int j = 1; j < NPAIR; j++) {
                    u64 xx = fmul2(xv[s][j], xv[s][j]);
                    acc = ffma2(xx, pack2f(sB[2 * j], sB[2 * j + 1]), acc);
                }
                float lo, hi; unpack2f(acc, lo, hi);
                AC2[s] = pack2f(lo + hi, 0.f);
                dens[s] = 0.f;
            }

            // prefetch row 0 (b-section + c)
            float4 q0, q1, q2, q3, q4; float ck;
            {
                const float4* row = (const float4*)(sB + 0 * ROWF);
                q0 = row[5]; q1 = row[6]; q2 = row[7]; q3 = row[8]; q4 = row[9];
                ck = sB[2 * DIMS];
            }

            for (int k = 0; k < KCOMP; k++) {
                const u64 G0 = pack2f(q0.x, q0.y), G1 = pack2f(q0.z, q0.w);
                const u64 G2 = pack2f(q1.x, q1.y), G3 = pack2f(q1.z, q1.w);
                const u64 G4 = pack2f(q2.x, q2.y), G5 = pack2f(q2.z, q2.w);
                const u64 G6 = pack2f(q3.x, q3.y), G7 = pack2f(q3.z, q3.w);
                const u64 G8 = pack2f(q4.x, q4.y), G9 = pack2f(q4.z, q4.w);
                const u64 CK2 = pack2f(0.f, ck);

                // prefetch next row while computing this one
                const int kn = (k + 1 < KCOMP) ? (k + 1) : 0;
                const float4* row = (const float4*)(sB + kn * ROWF);
                q0 = row[5]; q1 = row[6]; q2 = row[7]; q3 = row[8]; q4 = row[9];
                ck = sB[kn * ROWF + 2 * DIMS];

                #pragma unroll
                for (int s = 0; s < SPT; s++) {
                    u64 acc0 = ffma2(xv[s][0], G0, AC2[s]);
                    u64 acc1 = ffma2(xv[s][5], G5, CK2);
                    acc0 = ffma2(xv[s][1], G1, acc0);
                    acc1 = ffma2(xv[s][6], G6, acc1);
                    acc0 = ffma2(xv[s][2], G2, acc0);
                    acc1 = ffma2(xv[s][7], G7, acc1);
                    acc0 = ffma2(xv[s][3], G3, acc0);
                    acc1 = ffma2(xv[s][8], G8, acc1);
                    acc0 = ffma2(xv[s][4], G4, acc0);
                    acc1 = ffma2(xv[s][9], G9, acc1);
                    u64 acc = fadd2(acc0, acc1);
                    float lo, hi; unpack2f(acc, lo, hi);
                    dens[s] += ex2f(lo + hi);
                }
            }

            #pragma unroll
            for (int s = 0; s < SPT; s++)
                if (valid[s]) out[nn[s]] = logf(dens[s]);
        }
    } else {
        // ================= GENERAL PATH (full quadratic, Horner) =================
        for (int base = gtid; base < n_total; base += SPT * TT) {
            int nn[SPT]; bool valid[SPT];
            u64 xv[SPT][NPAIR];
            float dens[SPT];
            #pragma unroll
            for (int s = 0; s < SPT; s++) {
                nn[s] = base + s * TT;
                valid[s] = (nn[s] < n_total);
                const size_t idx = valid[s] ? (size_t)nn[s] : 0;
                const float2* xr = (const float2*)(sample + idx * DIMS);
                #pragma unroll
                for (int j = 0; j < NPAIR; j++) {
                    float2 p = xr[j];
                    xv[s][j] = pack2f(p.x, p.y);
                }
                dens[s] = 0.f;
            }

            for (int k = 0; k < KCOMP; k++) {
                const float4* row = (const float4*)(sB + k * ROWF);
                const float2 cc = *(const float2*)(sB + k * ROWF + 2 * DIMS);
                const u64 c2 = pack2f(cc.x, cc.y);
                u64 acc[SPT];
                #pragma unroll
                for (int s = 0; s < SPT; s++) acc[s] = c2;
                #pragma unroll
                for (int jj = 0; jj < 5; jj++) {
                    const float4 qa = row[jj];
                    const float4 qb = row[5 + jj];
                    const u64 A0 = pack2f(qa.x, qa.y), A1 = pack2f(qa.z, qa.w);
                    const u64 B0 = pack2f(qb.x, qb.y), B1 = pack2f(qb.z, qb.w);
                    #pragma unroll
                    for (int s = 0; s < SPT; s++) {
                        u64 tt0 = ffma2(xv[s][2 * jj], A0, B0);
                        acc[s] = ffma2(xv[s][2 * jj], tt0, acc[s]);
                        u64 tt1 = ffma2(xv[s][2 * jj + 1], A1, B1);
                        acc[s] = ffma2(xv[s][2 * jj + 1], tt1, acc[s]);
                    }
                }
                #pragma unroll
                for (int s = 0; s < SPT; s++) {
                    float lo, hi; unpack2f(acc[s], lo, hi);
                    dens[s] += ex2f(lo + hi);
                }
            }

            #pragma unroll
            for (int s = 0; s < SPT; s++)
                if (valid[s]) out[nn[s]] = logf(dens[s]);
        }
    }
}

extern "C" void kernel_launch(void* const* d_in, const int* in_sizes, int n_in,
                              void* d_out, int out_size) {
    const float* sample = (const float*)d_in[0];
    const float* alpha  = (const float*)d_in[1];
    const float* mu     = (const float*)d_in[2];
    const float* cov    = (const float*)d_in[3];
    float* out = (float*)d_out;

    const int n_total = in_sizes[0] / DIMS;

    int num_sms = 148;
    cudaDeviceGetAttribute(&num_sms, cudaDevAttrMultiProcessorCount, 0);
    gm_fused_kernel<<<2 * num_sms, 256>>>(sample, alpha, mu, cov, out, n_total);
}

// round 5
// speedup vs baseline: 2.5139x; 1.2720x over previous
#include <cuda_runtime.h>
#include <math.h>

#define DIMS 20
#define MULT 8
#define KCOMP 168
#define NPAIR (DIMS/2)
#define FROW 24              // fast row: g[20] | 0 | c | pad2
#define GROW 48              // general row: a[20] | b[20] | c | pad
#define LOG_NORM (-18.378770664093453f)
#define LN2F 0.6931471805599453f
#define EPS_VAR 1.0f
#define BASE_COV 0.1f
#define LOG2E 1.4426950408889634f

typedef unsigned long long u64;

// global staging written by prep kernel
__device__ float g_fast[4096];          // 168*24 rows + ainv[20] at 4032
__device__ float g_gen[KCOMP * GROW];   // fallback layout
__device__ int   g_flag;

__device__ __forceinline__ u64 pack2f(float lo, float hi) {
    u64 r; asm("mov.b64 %0, {%1, %2};" : "=l"(r) : "f"(lo), "f"(hi)); return r;
}
__device__ __forceinline__ void unpack2f(u64 v, float& lo, float& hi) {
    asm("mov.b64 {%0, %1}, %2;" : "=f"(lo), "=f"(hi) : "l"(v));
}
__device__ __forceinline__ u64 ffma2(u64 a, u64 b, u64 c) {
    u64 d; asm("fma.rn.f32x2 %0, %1, %2, %3;" : "=l"(d) : "l"(a), "l"(b), "l"(c)); return d;
}
__device__ __forceinline__ u64 fmul2(u64 a, u64 b) {
    u64 d; asm("mul.rn.f32x2 %0, %1, %2;" : "=l"(d) : "l"(a), "l"(b)); return d;
}
__device__ __forceinline__ float ex2f(float x) {
    float r; asm("ex2.approx.ftz.f32 %0, %1;" : "=f"(r) : "f"(x)); return r;
}

// ---------------------------------------------------------------------------
// Prep kernel (1 block): softmax, fold constants, emit both layouts + flag.
// Fast layout per k (24 floats): [ g_0..g_19, 0.0, c_k, 0, 0 ]
//   g_d = LOG2E * inv * mu ;  c_k = log2(w) - 0.5*log2det - 0.5*LOG2E*sum(mu^2 inv)
// ainv pairs at g_fast[4032..4051]: a_d = -0.5*LOG2E*inv0[d]  (for A_n)
// General layout (48 floats) identical to R4 (c has LOG2E*LOG_NORM folded).
// ---------------------------------------------------------------------------
__global__ void gm_prep_kernel(const float* __restrict__ alpha,
                               const float* __restrict__ mu,
                               const float* __restrict__ cov) {
    __shared__ float red[256];
    __shared__ int sflag;
    const int t = threadIdx.x;
    if (t == 0) sflag = 1;

    float av = (t < KCOMP) ? alpha[t] : -1e30f;
    red[t] = av; __syncthreads();
    for (int s = 128; s > 0; s >>= 1) { if (t < s) red[t] = fmaxf(red[t], red[t + s]); __syncthreads(); }
    const float mx = red[0]; __syncthreads();
    float ev = (t < KCOMP) ? expf(av - mx) : 0.f;
    red[t] = ev; __syncthreads();
    for (int s = 128; s > 0; s >>= 1) { if (t < s) red[t] += red[t + s]; __syncthreads(); }
    const float w = ev / red[0];

    if (t < KCOMP) {
        const int i = t / MULT;
        float sum_mu2inv = 0.f;
        int ok = 1;
        #pragma unroll
        for (int d = 0; d < DIMS; d++) {
            float sc = (d < i) ? EPS_VAR : 1.0f;
            float inv = 1.0f / (cov[t * DIMS + d] * sc);
            float inv0 = 1.0f / cov[d];
            ok &= (inv == inv0);
            float mm = mu[t * DIMS + d];
            g_fast[t * FROW + d]    = LOG2E * inv * mm;
            g_gen[t * GROW + d]        = -0.5f * LOG2E * inv;
            g_gen[t * GROW + DIMS + d] =  LOG2E * inv * mm;
            sum_mu2inv += mm * mm * inv;
        }
        float log2det = (float)i * log2f(EPS_VAR) + (float)(DIMS - i) * log2f(BASE_COV);
        float c = log2f(w) - 0.5f * log2det - 0.5f * LOG2E * sum_mu2inv;
        g_fast[t * FROW + 20] = 0.f;
        g_fast[t * FROW + 21] = c;
        g_fast[t * FROW + 22] = 0.f;
        g_fast[t * FROW + 23] = 0.f;
        g_gen[t * GROW + 2 * DIMS] = c + LOG2E * LOG_NORM;
        #pragma unroll
        for (int f = 2 * DIMS + 1; f < GROW; f++) g_gen[t * GROW + f] = 0.f;
        if (!ok) atomicAnd(&sflag, 0);
        if (t < DIMS) g_fast[KCOMP * FROW + t] = -0.5f * LOG2E * (1.0f / cov[t]);
    }
    __syncthreads();
    if (t == 0) {
        // zero pad region so stray vector loads are harmless
        for (int f = KCOMP * FROW + DIMS; f < 4096; f++) g_fast[f] = 0.f;
        g_flag = sflag;
    }
}

// ---------------------------------------------------------------------------
// Main kernel: flat launch, block = 128 threads, 2 samples/thread (chunk=256).
// Fast path: single 10-FFMA2 chain per (n,k); A_n factored out of the k-loop.
// ---------------------------------------------------------------------------
__global__ void __launch_bounds__(128, 5)
gm_main_kernel(const float* __restrict__ sample, float* __restrict__ out, int n_total) {
    __shared__ float sB[8192];           // 32 KB; fast path uses first 4096
    const int tid = threadIdx.x;
    const int flag = g_flag;

    if (flag) {
        const float4* src = (const float4*)g_fast;
        float4* dst = (float4*)sB;
        #pragma unroll
        for (int it = 0; it < 8; it++) dst[tid + 128 * it] = src[tid + 128 * it];
    } else {
        const float4* src = (const float4*)g_gen;
        float4* dst = (float4*)sB;
        for (int idx = tid; idx < KCOMP * GROW / 4; idx += 128) dst[idx] = src[idx];
    }
    __syncthreads();

    const int base = blockIdx.x * 256;
    int n0 = base + tid;
    int n1 = base + 128 + tid;
    const bool v0 = (n0 < n_total), v1 = (n1 < n_total);
    const size_t i0 = v0 ? (size_t)n0 : 0;
    const size_t i1 = v1 ? (size_t)n1 : 0;

    // sample rows are 80B = 5x16B -> ulonglong2 loads give f32x2 pairs directly
    u64 x0[NPAIR], x1[NPAIR];
    {
        const ulonglong2* p0 = (const ulonglong2*)(sample + i0 * DIMS);
        const ulonglong2* p1 = (const ulonglong2*)(sample + i1 * DIMS);
        #pragma unroll
        for (int j = 0; j < 5; j++) {
            ulonglong2 q0 = p0[j], q1 = p1[j];
            x0[2 * j] = q0.x; x0[2 * j + 1] = q0.y;
            x1[2 * j] = q1.x; x1[2 * j + 1] = q1.y;
        }
    }

    float dens0 = 0.f, dens1 = 0.f;

    if (flag) {
        // ---- A_n = sum_d a_d * x_d^2 (factored out of k-loop)
        const u64* ap = (const u64*)(sB + KCOMP * FROW);
        u64 aA0 = fmul2(fmul2(x0[0], x0[0]), ap[0]);
        u64 aA1 = fmul2(fmul2(x1[0], x1[0]), ap[0]);
        #pragma unroll
        for (int j = 1; j < NPAIR; j++) {
            aA0 = ffma2(fmul2(x0[j], x0[j]), ap[j], aA0);
            aA1 = ffma2(fmul2(x1[j], x1[j]), ap[j], aA1);
        }
        float al, ah, A0, A1;
        unpack2f(aA0, al, ah); A0 = al + ah;
        unpack2f(aA1, al, ah); A1 = al + ah;

        #pragma unroll 2
        for (int k = 0; k < KCOMP; k++) {
            const u64* R = (const u64*)(sB + k * FROW);   // g pairs [0..9], (0,c) at [10]
            const u64 ck2 = R[10];
            u64 acc0 = ffma2(x0[0], R[0], ck2);
            u64 acc1 = ffma2(x1[0], R[0], ck2);
            #pragma unroll
            for (int j = 1; j < NPAIR; j++) {
                acc0 = ffma2(x0[j], R[j], acc0);
                acc1 = ffma2(x1[j], R[j], acc1);
            }
            float l, h;
            unpack2f(acc0, l, h); dens0 += ex2f(l + h);
            unpack2f(acc1, l, h); dens1 += ex2f(l + h);
        }

        if (v0) out[n0] = fmaf(A0, LN2F, logf(dens0)) + LOG_NORM;
        if (v1) out[n1] = fmaf(A1, LN2F, logf(dens1)) + LOG_NORM;
    } else {
        // ---- general path: full Horner quadratic (c includes LOG2E*LOG_NORM)
        for (int k = 0; k < KCOMP; k++) {
            const u64* R = (const u64*)(sB + k * GROW);   // a[0..9], b[10..19], (c,0)[20]
            const u64 c2 = R[20];
            u64 acc0 = c2, acc1 = c2;
            #pragma unroll
            for (int j = 0; j < NPAIR; j++) {
                u64 t0 = ffma2(x0[j], R[j], R[10 + j]);
                acc0 = ffma2(x0[j], t0, acc0);
                u64 t1 = ffma2(x1[j], R[j], R[10 + j]);
                acc1 = ffma2(x1[j], t1, acc1);
            }
            float l, h;
            unpack2f(acc0, l, h); dens0 += ex2f(l + h);
            unpack2f(acc1, l, h); dens1 += ex2f(l + h);
        }
        if (v0) out[n0] = logf(dens0);
        if (v1) out[n1] = logf(dens1);
    }
}

extern "C" void kernel_launch(void* const* d_in, const int* in_sizes, int n_in,
                              void* d_out, int out_size) {
    const float* sample = (const float*)d_in[0];
    const float* alpha  = (const float*)d_in[1];
    const float* mu     = (const float*)d_in[2];
    const float* cov    = (const float*)d_in[3];
    float* out = (float*)d_out;

    const int n_total = in_sizes[0] / DIMS;
    const int blocks = (n_total + 255) / 256;     // 2048 for N=524288

    gm_prep_kernel<<<1, 256>>>(alpha, mu, cov);
    gm_main_kernel<<<blocks, 128>>>(sample, out, n_total);
}